// round 12
// baseline (speedup 1.0000x reference)
#include <cuda_runtime.h>
#include <math.h>

#define H      1024
#define SLEN   128
#define VOCAB  32000
#define STEPS  51
#define EOS_ID 2
#define GRID   512
#define TPB    256
#define NWARP  8
#define COMB0  256                   // blocks [256..511] compute ht2 columns in phase A
#define WCACHE_BYTES (NWARP * H * 4) // 32KB dynamic smem Whh cache
#define NGROUP 32                    // barrier groups
#define GBS    16                    // blocks per group (GRID/NGROUP)
#define CPAD   64                    // uints between counters (256B, distinct L2 lines)

// ---------------- persistent device state ----------------
__device__ float g_hbuf[2][H];
__device__ float g_c[H];
__device__ float g_hs[SLEN * H];
__device__ float g_gih[SLEN * 4 * H];   // precomputed Wih_e @ x_t
__device__ float g_U[H * SLEN];         // U[j][s] = Wtl_d[j] . hs[s]
__device__ float g_scores[SLEN];
__device__ float g_ht2[H];
__device__ float g_pval[GRID];
__device__ int   g_pidx[GRID];
__device__ unsigned int g_cnt1[NGROUP * CPAD];  // per-group arrival counters (monotonic per launch)
__device__ unsigned int g_root;                 // root counter
__device__ volatile unsigned int g_phase;       // published generation

__global__ void k_init() {
    const int t = threadIdx.x;       // 1024 threads
    g_hbuf[0][t] = 0.f;
    g_c[t] = 0.f;
    for (int i = t; i < NGROUP * CPAD; i += 1024) g_cnt1[i] = 0u;
    if (t == 0) { g_root = 0u; g_phase = 0u; }
}

// ---------------- two-level grid barrier: distinct-counter arrivals, single-word release -------
__device__ __forceinline__ void gbar(unsigned int& gen) {
    __syncthreads();
    gen += 1;
    if (threadIdx.x == 0) {
        asm volatile("fence.acq_rel.gpu;" ::: "memory");
        const int grp = blockIdx.x >> 4;             // 0..31
        unsigned int p = atomicAdd(&g_cnt1[grp * CPAD], 1u);
        if (p + 1u == GBS * gen) {                   // last of this group
            unsigned int q = atomicAdd(&g_root, 1u);
            if (q + 1u == NGROUP * gen) {            // last group overall
                asm volatile("fence.acq_rel.gpu;" ::: "memory");
                g_phase = gen;                       // release
            }
        }
        if (g_phase < gen) {
            while (*(volatile unsigned int*)&g_phase < gen) { }
        }
        asm volatile("fence.acq_rel.gpu;" ::: "memory");
    }
    __syncthreads();
}

__device__ __forceinline__ float sigf(float x) { return 1.f / (1.f + expf(-x)); }
__device__ __forceinline__ float dp4(float4 a, float4 b) {
    return a.x * b.x + a.y * b.y + a.z * b.z + a.w * b.w;
}
__device__ __forceinline__ float wred(float v) {
#pragma unroll
    for (int o = 16; o; o >>= 1) v += __shfl_down_sync(0xffffffffu, v, o);
    return v;
}

// ---------------- Whh smem cache: warp w owns gate row (g*H + j), j = b*2 + w/4, g = w%4 ----------
__device__ __forceinline__ void stage_whh(const float* __restrict__ Whh, float4* s_w)
{
    const int b = blockIdx.x, w = threadIdx.x >> 5, lane = threadIdx.x & 31;
    const int j = b * 2 + (w >> 2), g = w & 3;
    const float4* src = (const float4*)(Whh + (size_t)(g * H + j) * H);
#pragma unroll
    for (int i = 0; i < 8; i++) s_w[w * 256 + lane + 32 * i] = src[lane + 32 * i];
}

// Whh half from the smem cache
__device__ __forceinline__ void lstm_whh_sm(const float4* s_w,
                                            const float* __restrict__ hprev, float* s_g)
{
    const int w = threadIdx.x >> 5, lane = threadIdx.x & 31;
    const float4* h4 = (const float4*)hprev;
    float acc = 0.f;
#pragma unroll
    for (int i = 0; i < 8; i++) acc += dp4(s_w[w * 256 + lane + 32 * i], h4[lane + 32 * i]);
    acc = wred(acc);
    if (!lane) s_g[w] = acc;
}

__device__ __forceinline__ void lstm_pointwise(const float* __restrict__ bih,
                                               const float* __restrict__ bhh,
                                               float* __restrict__ hnext,
                                               float* __restrict__ hs_out, float* s_g)
{
    __syncthreads();
    const int tid = threadIdx.x;
    if (tid < 2) {
        const int j = blockIdx.x * 2 + tid;
        const int base = tid * 4;
        float gi = s_g[base + 0] + bih[j]         + bhh[j];
        float gf = s_g[base + 1] + bih[H + j]     + bhh[H + j];
        float gg = s_g[base + 2] + bih[2 * H + j] + bhh[2 * H + j];
        float go = s_g[base + 3] + bih[3 * H + j] + bhh[3 * H + j];
        float i_ = sigf(gi), f_ = sigf(gf), g_ = tanhf(gg), o_ = sigf(go);
        float c2 = f_ * g_c[j] + i_ * g_;
        g_c[j] = c2;
        float hn = o_ * tanhf(c2);
        hnext[j] = hn;
        if (hs_out) hs_out[j] = hn;
    }
}

// encoder pointwise: adds precomputed Wih@x term from g_gih[t]
__device__ __forceinline__ void lstm_pointwise_pre(int t,
                                                   const float* __restrict__ bih,
                                                   const float* __restrict__ bhh,
                                                   float* __restrict__ hnext,
                                                   float* __restrict__ hs_out, float* s_g)
{
    __syncthreads();
    const int tid = threadIdx.x;
    if (tid < 2) {
        const int j = blockIdx.x * 2 + tid;
        const int base = tid * 4;
        const float* pre = g_gih + (size_t)t * (4 * H);
        float gi = s_g[base + 0] + pre[j]         + bih[j]         + bhh[j];
        float gf = s_g[base + 1] + pre[H + j]     + bih[H + j]     + bhh[H + j];
        float gg = s_g[base + 2] + pre[2 * H + j] + bih[2 * H + j] + bhh[2 * H + j];
        float go = s_g[base + 3] + pre[3 * H + j] + bih[3 * H + j] + bhh[3 * H + j];
        float i_ = sigf(gi), f_ = sigf(gf), g_ = tanhf(gg), o_ = sigf(go);
        float c2 = f_ * g_c[j] + i_ * g_;
        g_c[j] = c2;
        float hn = o_ * tanhf(c2);
        hnext[j] = hn;
        if (hs_out) hs_out[j] = hn;
    }
}

// full LSTM cell: Wih from global, Whh from the smem cache
__device__ __forceinline__ void lstm_full_sm(const float* __restrict__ Wih,
                                             const float4* s_w,
                                             const float* __restrict__ bih,
                                             const float* __restrict__ bhh,
                                             const float* __restrict__ xrow,
                                             const float* __restrict__ hprev,
                                             float* __restrict__ hnext,
                                             float* __restrict__ hs_out, float* s_g)
{
    const int b = blockIdx.x, w = threadIdx.x >> 5, lane = threadIdx.x & 31;
    const int j = b * 2 + (w >> 2), g = w & 3;
    const float4* wi = (const float4*)(Wih + (size_t)(g * H + j) * H);
    const float4* x4 = (const float4*)xrow;
    const float4* h4 = (const float4*)hprev;
    float acc = 0.f;
#pragma unroll
    for (int i = 0; i < 8; i++) acc += dp4(wi[lane + 32 * i], x4[lane + 32 * i]);
#pragma unroll
    for (int i = 0; i < 8; i++) acc += dp4(s_w[w * 256 + lane + 32 * i], h4[lane + 32 * i]);
    acc = wred(acc);
    if (!lane) s_g[w] = acc;
    lstm_pointwise(bih, bhh, hnext, hs_out, s_g);
}

// ---------------- attention scores: blocks 496..511, one warp per source row ----------------
__device__ __forceinline__ void scores_piece(const float* __restrict__ ht)
{
    const int b = blockIdx.x;
    if (b < GRID - 16) return;
    const int w = threadIdx.x >> 5, lane = threadIdx.x & 31;
    const int s = (b - (GRID - 16)) * NWARP + w;     // 0..127
    const float4* r  = (const float4*)(g_hs + (size_t)s * H);
    const float4* h4 = (const float4*)ht;
    float acc = 0.f;
#pragma unroll
    for (int i = 0; i < 8; i++) acc += dp4(r[lane + 32 * i], h4[lane + 32 * i]);
    acc = wred(acc);
    if (!lane) g_scores[s] = acc;
}

// ---------------- U precompute: blocks 0..127, warp holds Wtl_d row j in regs ----------------
__device__ __forceinline__ void u_precompute(const float* __restrict__ Wtl)
{
    const int b = blockIdx.x;
    if (b >= 128) return;
    const int w = threadIdx.x >> 5, lane = threadIdx.x & 31;
    const int j = b * NWARP + w;                     // 0..1023
    const float4* wr = (const float4*)(Wtl + (size_t)j * 2 * H);   // first half = d-part
    float4 wreg[8];
#pragma unroll
    for (int q = 0; q < 8; q++) wreg[q] = wr[lane + 32 * q];
    for (int s = 0; s < SLEN; s += 2) {
        const float4* h0 = (const float4*)(g_hs + (size_t)s * H);
        const float4* h1 = h0 + (H / 4);
        float a0 = 0.f, a1 = 0.f;
#pragma unroll
        for (int q = 0; q < 8; q++) {
            const int k = lane + 32 * q;
            a0 += dp4(wreg[q], h0[k]);
            a1 += dp4(wreg[q], h1[k]);
        }
        a0 = wred(a0);
        a1 = wred(a1);
        if (!lane) {
            g_U[(size_t)j * SLEN + s]     = a0;
            g_U[(size_t)j * SLEN + s + 1] = a1;
        }
    }
}

// ---------------- combine: softmax + ht2[j] = tanh(inv*Sum a~_s U[j,s] + V_j.ht + b_j) -----------
__device__ __forceinline__ void combine_piece(const float* __restrict__ Wtl,
                                              const float* __restrict__ btl,
                                              const float* __restrict__ ht,
                                              float* s_sc, float* s_a, float* s_scalar)
{
    const int b = blockIdx.x;
    if (b < COMB0) return;
    const int tid = threadIdx.x, w = tid >> 5, lane = tid & 31;
    if (tid < SLEN) s_sc[tid] = g_scores[tid];
    __syncthreads();
    if (w == 0) {
        float m = -INFINITY;
#pragma unroll
        for (int q = 0; q < 4; q++) m = fmaxf(m, s_sc[lane + 32 * q]);
#pragma unroll
        for (int o = 16; o; o >>= 1) m = fmaxf(m, __shfl_xor_sync(0xffffffffu, m, o));
        float sum = 0.f;
#pragma unroll
        for (int q = 0; q < 4; q++) {
            float e = expf(s_sc[lane + 32 * q] - m);
            s_a[lane + 32 * q] = e;
            sum += e;
        }
#pragma unroll
        for (int o = 16; o; o >>= 1) sum += __shfl_xor_sync(0xffffffffu, sum, o);
        if (!lane) s_scalar[0] = 1.f / sum;
    }
    __syncthreads();
    if (w < 4) {
        const int j = (b - COMB0) * 4 + w;           // 0..1023
        const float4* vr = (const float4*)(Wtl + (size_t)j * 2 * H + H);  // second half
        const float4* h4 = (const float4*)ht;
        float acc = 0.f;
#pragma unroll
        for (int i = 0; i < 8; i++) acc += dp4(vr[lane + 32 * i], h4[lane + 32 * i]);
        float4 u = ((const float4*)(g_U + (size_t)j * SLEN))[lane];
        float au = u.x * s_a[lane * 4] + u.y * s_a[lane * 4 + 1]
                 + u.z * s_a[lane * 4 + 2] + u.w * s_a[lane * 4 + 3];
        float tot = wred(au * s_scalar[0] + acc);
        if (!lane) g_ht2[j] = tanhf(tot + btl[j]);
    }
}

// ---------------- logits GEMV (champion mapping + 2-row interleave) ----------------
__device__ __forceinline__ void logits_piece(const float* __restrict__ W,
                                             const float* __restrict__ bias,
                                             const float* __restrict__ vec,
                                             float* __restrict__ out_logits,
                                             float* s_v, int* s_i)
{
    const int tid = threadIdx.x, w = tid >> 5, lane = tid & 31;
    const float4* x4 = (const float4*)vec;
    float4 v[8];
#pragma unroll
    for (int q = 0; q < 8; q++) v[q] = x4[lane + 32 * q];
    const int gw = blockIdx.x * NWARP + w;           // 0..4095
    float best = -INFINITY; int bidx = VOCAB;
#pragma unroll
    for (int p = 0; p < 4; p++) {
        const int r0 = gw + 8192 * p;
        const int r1 = r0 + 4096;
        const float4* w0 = (const float4*)(W + (size_t)r0 * H);
        if (r1 < VOCAB) {
            const float4* w1 = (const float4*)(W + (size_t)r1 * H);
            float acc0 = 0.f, acc1 = 0.f;
#pragma unroll
            for (int q = 0; q < 8; q++) {
                const int k = lane + 32 * q;
                float4 a = __ldcs(w0 + k);
                float4 bb = __ldcs(w1 + k);
                acc0 += dp4(a, v[q]);
                acc1 += dp4(bb, v[q]);
            }
            acc0 = wred(acc0);
            acc1 = wred(acc1);
            if (!lane) {
                float l0 = acc0 + bias[r0];
                float l1 = acc1 + bias[r1];
                if (out_logits) { __stcs(out_logits + r0, l0); __stcs(out_logits + r1, l1); }
                if (l0 > best) { best = l0; bidx = r0; }
                if (l1 > best) { best = l1; bidx = r1; }
            }
        } else {
            float acc0 = 0.f;
#pragma unroll
            for (int q = 0; q < 8; q++) acc0 += dp4(__ldcs(w0 + lane + 32 * q), v[q]);
            acc0 = wred(acc0);
            if (!lane) {
                float l0 = acc0 + bias[r0];
                if (out_logits) __stcs(out_logits + r0, l0);
                if (l0 > best) { best = l0; bidx = r0; }
            }
        }
    }
    if (!lane) { s_v[w] = best; s_i[w] = bidx; }
    __syncthreads();
    if (tid == 0) {
        float bv = s_v[0]; int bi = s_i[0];
#pragma unroll
        for (int q = 1; q < NWARP; q++)
            if (s_v[q] > bv || (s_v[q] == bv && s_i[q] < bi)) { bv = s_v[q]; bi = s_i[q]; }
        g_pval[blockIdx.x] = bv; g_pidx[blockIdx.x] = bi;
    }
}

// ---------------- replicated finalize: EVERY block computes wid/done locally ----------------
__device__ __forceinline__ void finalize_repl(int step, int& wid, int& done,
                                              float* __restrict__ out_toks,
                                              float* s_v, int* s_i)
{
    const int t = threadIdx.x;
    float bv = g_pval[t];       int bi = g_pidx[t];
    float v2 = g_pval[t + 256]; int i2 = g_pidx[t + 256];
    if (v2 > bv || (v2 == bv && i2 < bi)) { bv = v2; bi = i2; }
    s_v[t] = bv; s_i[t] = bi;
    __syncthreads();
    for (int st = 128; st > 0; st >>= 1) {
        if (t < st) {
            float v = s_v[t + st]; int i = s_i[t + st];
            if (v > s_v[t] || (v == s_v[t] && i < s_i[t])) { s_v[t] = v; s_i[t] = i; }
        }
        __syncthreads();
    }
    const int wn = s_i[0];
    const int is_eos = (wn == EOS_ID);
    if (step >= 0 && blockIdx.x == 4 && t == 0)
        out_toks[step] = (float)((done || is_eos) ? -1 : wn);
    wid = wn;
    done = done | is_eos;
    __syncthreads();
}

// ---------------- the whole model, one persistent kernel ----------------
__global__ void __launch_bounds__(TPB, 4) k_main(
    const int* __restrict__ src,
    const float* __restrict__ embI,
    const float* __restrict__ WihE, const float* __restrict__ WhhE,
    const float* __restrict__ bihE, const float* __restrict__ bhhE,
    const float* __restrict__ Wli,  const float* __restrict__ bli,
    const float* __restrict__ embT,
    const float* __restrict__ WihD, const float* __restrict__ WhhD,
    const float* __restrict__ bihD, const float* __restrict__ bhhD,
    const float* __restrict__ Wlt,  const float* __restrict__ blt,
    const float* __restrict__ Wtl,  const float* __restrict__ btl,
    float* __restrict__ out)
{
    extern __shared__ float4 s_w[];  // 32KB Whh row cache (per-block rows)
    __shared__ float s_g[8];
    __shared__ float s_v[256];
    __shared__ int   s_i[256];
    __shared__ float s_sc[SLEN];
    __shared__ float s_a[SLEN];
    __shared__ float s_scalar[1];

    unsigned int gen = 0;
    float* out_logits = out + STEPS;
    const int b = blockIdx.x;
    const int w = threadIdx.x >> 5, lane = threadIdx.x & 31;
    int wid = 0, done = 0;

    // ---- P0: precompute Wih_e @ x_t for all 128 tokens + stage WhhE rows into smem ----
    stage_whh(WhhE, s_w);
    {
        const int r = b * NWARP + w;
        const float4* wr = (const float4*)(WihE + (size_t)r * H);
        float4 wreg[8];
#pragma unroll
        for (int q = 0; q < 8; q++) wreg[q] = wr[lane + 32 * q];
        for (int t = 0; t < SLEN; t += 2) {
            const float4* x0 = (const float4*)(embI + (size_t)src[t]     * H);
            const float4* x1 = (const float4*)(embI + (size_t)src[t + 1] * H);
            float a0 = 0.f, a1 = 0.f;
#pragma unroll
            for (int q = 0; q < 8; q++) {
                const int k = lane + 32 * q;
                a0 += dp4(wreg[q], x0[k]);
                a1 += dp4(wreg[q], x1[k]);
            }
            a0 = wred(a0);
            a1 = wred(a1);
            if (!lane) {
                g_gih[(size_t)t       * (4 * H) + r] = a0;
                g_gih[(size_t)(t + 1) * (4 * H) + r] = a1;
            }
        }
    }
    gbar(gen);

    // ---- encoder: 128 steps, Whh GEMV from SMEM + precomputed Wih term ----
    for (int t = 0; t < SLEN; t++) {
        lstm_whh_sm(s_w, g_hbuf[t & 1], s_g);
        lstm_pointwise_pre(t, bihE, bhhE, g_hbuf[(t + 1) & 1], g_hs + (size_t)t * H, s_g);
        gbar(gen);
    }
    // final encoder h in g_hbuf[0], c in g_c

    // ---- E1: first-word logits; re-stage the cache with WhhD for the decoder ----
    logits_piece(Wli, bli, g_hbuf[0], nullptr, s_v, s_i);
    __syncthreads();
    stage_whh(WhhD, s_w);
    gbar(gen);

    // ---- E2: replicated finalize -> wid0; initial decoder LSTM -> ht(0); U precompute ----
    finalize_repl(-1, wid, done, out, s_v, s_i);
    lstm_full_sm(WihD, s_w, bihD, bhhD, embT + (size_t)wid * H,
                 g_hbuf[0], g_hbuf[1], nullptr, s_g);
    u_precompute(Wtl);
    gbar(gen);

    // ---- E3: scores(0) ----
    scores_piece(g_hbuf[1]);
    gbar(gen);

    // ---- decode loop: 2 grid barriers per step ----
    int cur = 1;                                    // ht(t) = g_hbuf[cur]
    for (int t = 0; t < STEPS; t++) {
        const float* ht  = g_hbuf[cur];
        float*       htn = g_hbuf[1 - cur];

        // Phase A: finalize(t-1); full LSTM (Whh smem) -> ht(t+1); combine -> ht2(t)
        if (t > 0) finalize_repl(t - 1, wid, done, out, s_v, s_i);
        lstm_full_sm(WihD, s_w, bihD, bhhD, embT + (size_t)wid * H, ht, htn, nullptr, s_g);
        combine_piece(Wtl, btl, ht, s_sc, s_a, s_scalar);
        gbar(gen);

        // Phase B: logits(t) from ht2 (all blocks) || scores(t+1) (blocks 496..511)
        scores_piece(htn);
        logits_piece(Wlt, blt, g_ht2, out_logits + (size_t)t * VOCAB, s_v, s_i);
        gbar(gen);

        cur ^= 1;
    }
    finalize_repl(STEPS - 1, wid, done, out, s_v, s_i);
}

// ---------------- host orchestration ----------------
extern "C" void kernel_launch(void* const* d_in, const int* in_sizes, int n_in,
                              void* d_out, int out_size)
{
    const int*   src  = (const int*)  d_in[0];
    const float* embI = (const float*)d_in[1];
    const float* WihE = (const float*)d_in[2];
    const float* WhhE = (const float*)d_in[3];
    const float* bihE = (const float*)d_in[4];
    const float* bhhE = (const float*)d_in[5];
    const float* Wli  = (const float*)d_in[6];
    const float* bli  = (const float*)d_in[7];
    const float* embT = (const float*)d_in[8];
    const float* WihD = (const float*)d_in[9];
    const float* WhhD = (const float*)d_in[10];
    const float* bihD = (const float*)d_in[11];
    const float* bhhD = (const float*)d_in[12];
    const float* Wlt  = (const float*)d_in[13];
    const float* blt  = (const float*)d_in[14];
    const float* Wtl  = (const float*)d_in[15];
    const float* btl  = (const float*)d_in[16];

    k_init<<<1, 1024>>>();
    k_main<<<GRID, TPB, WCACHE_BYTES>>>(src, embI, WihE, WhhE, bihE, bhhE, Wli, bli, embT,
                                        WihD, WhhD, bihD, bhhD, Wlt, blt, Wtl, btl,
                                        (float*)d_out);
}

// round 13
// speedup vs baseline: 1.2744x; 1.2744x over previous
#include <cuda_runtime.h>
#include <cuda_fp16.h>
#include <math.h>

#define H      1024
#define SLEN   128
#define VOCAB  32000
#define STEPS  51
#define EOS_ID 2
#define GRID   512
#define TPB    256
#define NWARP  8
#define COMB0  256                   // blocks [256..511] compute ht2 columns in phase A
#define WCACHE_BYTES (NWARP * H * 4) // 32KB dynamic smem Whh cache
#define NU4    (VOCAB * H / 8)       // uint4 count of one fp16 weight matrix (64MB)

// ---------------- persistent device state ----------------
__device__ float g_hbuf[2][H];
__device__ float g_c[H];
__device__ float g_hs[SLEN * H];
__device__ float g_gih[SLEN * 4 * H];   // precomputed Wih_e @ x_t
__device__ float g_U[H * SLEN];         // U[j][s] = Wtl_d[j] . hs[s]
__device__ float g_scores[SLEN];
__device__ float g_ht2[H];
__device__ float g_pval[GRID];
__device__ int   g_pidx[GRID];
__device__ unsigned int g_bar_count;
__device__ uint4 g_wlt16[NU4];          // W_lt in fp16 (half2-packed), 64MB bss
__device__ uint4 g_wli16[NU4];          // W_li in fp16, 64MB bss

__global__ void k_init() {
    const int t = threadIdx.x;       // 1024 threads
    g_hbuf[0][t] = 0.f;
    g_c[t] = 0.f;
    if (t == 0) g_bar_count = 0u;
}

// ---------------- flat grid barrier (round-10 proven) ----------------
__device__ __forceinline__ void gbar(unsigned int& gen) {
    __syncthreads();
    gen += GRID;
    if (threadIdx.x == 0) {
        asm volatile("fence.acq_rel.gpu;" ::: "memory");
        unsigned int prev = atomicAdd(&g_bar_count, 1u);
        if (prev + 1u != gen) {
            while (*(volatile unsigned int*)&g_bar_count < gen) { }
        }
        asm volatile("fence.acq_rel.gpu;" ::: "memory");
    }
    __syncthreads();
}

__device__ __forceinline__ float sigf(float x) { return 1.f / (1.f + expf(-x)); }
__device__ __forceinline__ float dp4(float4 a, float4 b) {
    return a.x * b.x + a.y * b.y + a.z * b.z + a.w * b.w;
}
__device__ __forceinline__ float wred(float v) {
#pragma unroll
    for (int o = 16; o; o >>= 1) v += __shfl_down_sync(0xffffffffu, v, o);
    return v;
}

// ---------------- fp32 -> fp16 weight conversion (grid-stride, deterministic) ----------------
__device__ __forceinline__ void convert_w16(const float* __restrict__ Wsrc, uint4* __restrict__ dst)
{
    const int gtid = blockIdx.x * TPB + threadIdx.x;     // 0..131071
    const float4* src4 = (const float4*)Wsrc;
    uint2* dst2 = (uint2*)dst;
    for (int i = gtid; i < VOCAB * H / 4; i += GRID * TPB) {
        float4 f = __ldcs(src4 + i);
        __half2 h01 = __floats2half2_rn(f.x, f.y);
        __half2 h23 = __floats2half2_rn(f.z, f.w);
        uint2 u;
        u.x = *reinterpret_cast<unsigned int*>(&h01);
        u.y = *reinterpret_cast<unsigned int*>(&h23);
        __stcs(dst2 + i, u);
    }
}

// ---------------- Whh smem cache: warp w owns gate row (g*H + j), j = b*2 + w/4, g = w%4 ----------
__device__ __forceinline__ void stage_whh(const float* __restrict__ Whh, float4* s_w)
{
    const int b = blockIdx.x, w = threadIdx.x >> 5, lane = threadIdx.x & 31;
    const int j = b * 2 + (w >> 2), g = w & 3;
    const float4* src = (const float4*)(Whh + (size_t)(g * H + j) * H);
#pragma unroll
    for (int i = 0; i < 8; i++) s_w[w * 256 + lane + 32 * i] = src[lane + 32 * i];
}

__device__ __forceinline__ void lstm_whh_sm(const float4* s_w,
                                            const float* __restrict__ hprev, float* s_g)
{
    const int w = threadIdx.x >> 5, lane = threadIdx.x & 31;
    const float4* h4 = (const float4*)hprev;
    float acc = 0.f;
#pragma unroll
    for (int i = 0; i < 8; i++) acc += dp4(s_w[w * 256 + lane + 32 * i], h4[lane + 32 * i]);
    acc = wred(acc);
    if (!lane) s_g[w] = acc;
}

__device__ __forceinline__ void lstm_pointwise(const float* __restrict__ bih,
                                               const float* __restrict__ bhh,
                                               float* __restrict__ hnext,
                                               float* __restrict__ hs_out, float* s_g)
{
    __syncthreads();
    const int tid = threadIdx.x;
    if (tid < 2) {
        const int j = blockIdx.x * 2 + tid;
        const int base = tid * 4;
        float gi = s_g[base + 0] + bih[j]         + bhh[j];
        float gf = s_g[base + 1] + bih[H + j]     + bhh[H + j];
        float gg = s_g[base + 2] + bih[2 * H + j] + bhh[2 * H + j];
        float go = s_g[base + 3] + bih[3 * H + j] + bhh[3 * H + j];
        float i_ = sigf(gi), f_ = sigf(gf), g_ = tanhf(gg), o_ = sigf(go);
        float c2 = f_ * g_c[j] + i_ * g_;
        g_c[j] = c2;
        float hn = o_ * tanhf(c2);
        hnext[j] = hn;
        if (hs_out) hs_out[j] = hn;
    }
}

__device__ __forceinline__ void lstm_pointwise_pre(int t,
                                                   const float* __restrict__ bih,
                                                   const float* __restrict__ bhh,
                                                   float* __restrict__ hnext,
                                                   float* __restrict__ hs_out, float* s_g)
{
    __syncthreads();
    const int tid = threadIdx.x;
    if (tid < 2) {
        const int j = blockIdx.x * 2 + tid;
        const int base = tid * 4;
        const float* pre = g_gih + (size_t)t * (4 * H);
        float gi = s_g[base + 0] + pre[j]         + bih[j]         + bhh[j];
        float gf = s_g[base + 1] + pre[H + j]     + bih[H + j]     + bhh[H + j];
        float gg = s_g[base + 2] + pre[2 * H + j] + bih[2 * H + j] + bhh[2 * H + j];
        float go = s_g[base + 3] + pre[3 * H + j] + bih[3 * H + j] + bhh[3 * H + j];
        float i_ = sigf(gi), f_ = sigf(gf), g_ = tanhf(gg), o_ = sigf(go);
        float c2 = f_ * g_c[j] + i_ * g_;
        g_c[j] = c2;
        float hn = o_ * tanhf(c2);
        hnext[j] = hn;
        if (hs_out) hs_out[j] = hn;
    }
}

__device__ __forceinline__ void lstm_full_sm(const float* __restrict__ Wih,
                                             const float4* s_w,
                                             const float* __restrict__ bih,
                                             const float* __restrict__ bhh,
                                             const float* __restrict__ xrow,
                                             const float* __restrict__ hprev,
                                             float* __restrict__ hnext,
                                             float* __restrict__ hs_out, float* s_g)
{
    const int b = blockIdx.x, w = threadIdx.x >> 5, lane = threadIdx.x & 31;
    const int j = b * 2 + (w >> 2), g = w & 3;
    const float4* wi = (const float4*)(Wih + (size_t)(g * H + j) * H);
    const float4* x4 = (const float4*)xrow;
    const float4* h4 = (const float4*)hprev;
    float acc = 0.f;
#pragma unroll
    for (int i = 0; i < 8; i++) acc += dp4(wi[lane + 32 * i], x4[lane + 32 * i]);
#pragma unroll
    for (int i = 0; i < 8; i++) acc += dp4(s_w[w * 256 + lane + 32 * i], h4[lane + 32 * i]);
    acc = wred(acc);
    if (!lane) s_g[w] = acc;
    lstm_pointwise(bih, bhh, hnext, hs_out, s_g);
}

// ---------------- attention scores: blocks 496..511, one warp per source row ----------------
__device__ __forceinline__ void scores_piece(const float* __restrict__ ht)
{
    const int b = blockIdx.x;
    if (b < GRID - 16) return;
    const int w = threadIdx.x >> 5, lane = threadIdx.x & 31;
    const int s = (b - (GRID - 16)) * NWARP + w;     // 0..127
    const float4* r  = (const float4*)(g_hs + (size_t)s * H);
    const float4* h4 = (const float4*)ht;
    float acc = 0.f;
#pragma unroll
    for (int i = 0; i < 8; i++) acc += dp4(r[lane + 32 * i], h4[lane + 32 * i]);
    acc = wred(acc);
    if (!lane) g_scores[s] = acc;
}

// ---------------- U precompute: blocks 0..127, warp holds Wtl_d row j in regs ----------------
__device__ __forceinline__ void u_precompute(const float* __restrict__ Wtl)
{
    const int b = blockIdx.x;
    if (b >= 128) return;
    const int w = threadIdx.x >> 5, lane = threadIdx.x & 31;
    const int j = b * NWARP + w;                     // 0..1023
    const float4* wr = (const float4*)(Wtl + (size_t)j * 2 * H);   // first half = d-part
    float4 wreg[8];
#pragma unroll
    for (int q = 0; q < 8; q++) wreg[q] = wr[lane + 32 * q];
    for (int s = 0; s < SLEN; s += 2) {
        const float4* h0 = (const float4*)(g_hs + (size_t)s * H);
        const float4* h1 = h0 + (H / 4);
        float a0 = 0.f, a1 = 0.f;
#pragma unroll
        for (int q = 0; q < 8; q++) {
            const int k = lane + 32 * q;
            a0 += dp4(wreg[q], h0[k]);
            a1 += dp4(wreg[q], h1[k]);
        }
        a0 = wred(a0);
        a1 = wred(a1);
        if (!lane) {
            g_U[(size_t)j * SLEN + s]     = a0;
            g_U[(size_t)j * SLEN + s + 1] = a1;
        }
    }
}

// ---------------- combine: softmax + ht2[j] = tanh(inv*Sum a~_s U[j,s] + V_j.ht + b_j) -----------
__device__ __forceinline__ void combine_piece(const float* __restrict__ Wtl,
                                              const float* __restrict__ btl,
                                              const float* __restrict__ ht,
                                              float* s_sc, float* s_a, float* s_scalar)
{
    const int b = blockIdx.x;
    if (b < COMB0) return;
    const int tid = threadIdx.x, w = tid >> 5, lane = tid & 31;
    if (tid < SLEN) s_sc[tid] = g_scores[tid];
    __syncthreads();
    if (w == 0) {
        float m = -INFINITY;
#pragma unroll
        for (int q = 0; q < 4; q++) m = fmaxf(m, s_sc[lane + 32 * q]);
#pragma unroll
        for (int o = 16; o; o >>= 1) m = fmaxf(m, __shfl_xor_sync(0xffffffffu, m, o));
        float sum = 0.f;
#pragma unroll
        for (int q = 0; q < 4; q++) {
            float e = expf(s_sc[lane + 32 * q] - m);
            s_a[lane + 32 * q] = e;
            sum += e;
        }
#pragma unroll
        for (int o = 16; o; o >>= 1) sum += __shfl_xor_sync(0xffffffffu, sum, o);
        if (!lane) s_scalar[0] = 1.f / sum;
    }
    __syncthreads();
    if (w < 4) {
        const int j = (b - COMB0) * 4 + w;           // 0..1023
        const float4* vr = (const float4*)(Wtl + (size_t)j * 2 * H + H);  // second half
        const float4* h4 = (const float4*)ht;
        float acc = 0.f;
#pragma unroll
        for (int i = 0; i < 8; i++) acc += dp4(vr[lane + 32 * i], h4[lane + 32 * i]);
        float4 u = ((const float4*)(g_U + (size_t)j * SLEN))[lane];
        float au = u.x * s_a[lane * 4] + u.y * s_a[lane * 4 + 1]
                 + u.z * s_a[lane * 4 + 2] + u.w * s_a[lane * 4 + 3];
        float tot = wred(au * s_scalar[0] + acc);
        if (!lane) g_ht2[j] = tanhf(tot + btl[j]);
    }
}

// ---------------- logits GEMV over fp16 weights (slab mapping + 2-row interleave) ----------------
// warp gw owns rows {gw + 4096*i}; rows are 1024 halfs = 128 uint4 each.
__device__ __forceinline__ void logits_piece_h(const uint4* __restrict__ W16,
                                               const float* __restrict__ bias,
                                               const float* __restrict__ vec,
                                               float* __restrict__ out_logits,
                                               float* s_v, int* s_i)
{
    const int tid = threadIdx.x, w = tid >> 5, lane = tid & 31;
    const float4* x4 = (const float4*)vec;
    // lane covers columns [(lane+32q)*8, +8) for q=0..3
    float v[32];
#pragma unroll
    for (int q = 0; q < 4; q++) {
        float4 t0 = x4[(lane + 32 * q) * 2];
        float4 t1 = x4[(lane + 32 * q) * 2 + 1];
        v[q * 8 + 0] = t0.x; v[q * 8 + 1] = t0.y; v[q * 8 + 2] = t0.z; v[q * 8 + 3] = t0.w;
        v[q * 8 + 4] = t1.x; v[q * 8 + 5] = t1.y; v[q * 8 + 6] = t1.z; v[q * 8 + 7] = t1.w;
    }
    const int gw = blockIdx.x * NWARP + w;           // 0..4095
    float best = -INFINITY; int bidx = VOCAB;
#pragma unroll
    for (int p = 0; p < 4; p++) {
        const int r0 = gw + 8192 * p;
        const int r1 = r0 + 4096;
        const uint4* w0 = W16 + (size_t)r0 * (H / 8);
        if (r1 < VOCAB) {
            const uint4* w1 = W16 + (size_t)r1 * (H / 8);
            float acc0 = 0.f, acc1 = 0.f;
#pragma unroll
            for (int q = 0; q < 4; q++) {
                uint4 a = __ldcs(w0 + lane + 32 * q);
                uint4 b = __ldcs(w1 + lane + 32 * q);
                const __half2* ah = (const __half2*)&a;
                const __half2* bh = (const __half2*)&b;
#pragma unroll
                for (int i = 0; i < 4; i++) {
                    float2 fa = __half22float2(ah[i]);
                    float2 fb = __half22float2(bh[i]);
                    acc0 += fa.x * v[q * 8 + 2 * i] + fa.y * v[q * 8 + 2 * i + 1];
                    acc1 += fb.x * v[q * 8 + 2 * i] + fb.y * v[q * 8 + 2 * i + 1];
                }
            }
            acc0 = wred(acc0);
            acc1 = wred(acc1);
            if (!lane) {
                float l0 = acc0 + bias[r0];
                float l1 = acc1 + bias[r1];
                if (out_logits) { __stcs(out_logits + r0, l0); __stcs(out_logits + r1, l1); }
                if (l0 > best) { best = l0; bidx = r0; }   // r0 < r1 preserves tie-break
                if (l1 > best) { best = l1; bidx = r1; }
            }
        } else {
            float acc0 = 0.f;
#pragma unroll
            for (int q = 0; q < 4; q++) {
                uint4 a = __ldcs(w0 + lane + 32 * q);
                const __half2* ah = (const __half2*)&a;
#pragma unroll
                for (int i = 0; i < 4; i++) {
                    float2 fa = __half22float2(ah[i]);
                    acc0 += fa.x * v[q * 8 + 2 * i] + fa.y * v[q * 8 + 2 * i + 1];
                }
            }
            acc0 = wred(acc0);
            if (!lane) {
                float l0 = acc0 + bias[r0];
                if (out_logits) __stcs(out_logits + r0, l0);
                if (l0 > best) { best = l0; bidx = r0; }
            }
        }
    }
    if (!lane) { s_v[w] = best; s_i[w] = bidx; }
    __syncthreads();
    if (tid == 0) {
        float bv = s_v[0]; int bi = s_i[0];
#pragma unroll
        for (int q = 1; q < NWARP; q++)
            if (s_v[q] > bv || (s_v[q] == bv && s_i[q] < bi)) { bv = s_v[q]; bi = s_i[q]; }
        g_pval[blockIdx.x] = bv; g_pidx[blockIdx.x] = bi;
    }
}

// ---------------- replicated finalize: EVERY block computes wid/done locally ----------------
__device__ __forceinline__ void finalize_repl(int step, int& wid, int& done,
                                              float* __restrict__ out_toks,
                                              float* s_v, int* s_i)
{
    const int t = threadIdx.x;
    float bv = g_pval[t];       int bi = g_pidx[t];
    float v2 = g_pval[t + 256]; int i2 = g_pidx[t + 256];
    if (v2 > bv || (v2 == bv && i2 < bi)) { bv = v2; bi = i2; }
    s_v[t] = bv; s_i[t] = bi;
    __syncthreads();
    for (int st = 128; st > 0; st >>= 1) {
        if (t < st) {
            float v = s_v[t + st]; int i = s_i[t + st];
            if (v > s_v[t] || (v == s_v[t] && i < s_i[t])) { s_v[t] = v; s_i[t] = i; }
        }
        __syncthreads();
    }
    const int wn = s_i[0];
    const int is_eos = (wn == EOS_ID);
    if (step >= 0 && blockIdx.x == 4 && t == 0)
        out_toks[step] = (float)((done || is_eos) ? -1 : wn);
    wid = wn;
    done = done | is_eos;
    __syncthreads();
}

// ---------------- the whole model, one persistent kernel ----------------
__global__ void __launch_bounds__(TPB, 4) k_main(
    const int* __restrict__ src,
    const float* __restrict__ embI,
    const float* __restrict__ WihE, const float* __restrict__ WhhE,
    const float* __restrict__ bihE, const float* __restrict__ bhhE,
    const float* __restrict__ Wli,  const float* __restrict__ bli,
    const float* __restrict__ embT,
    const float* __restrict__ WihD, const float* __restrict__ WhhD,
    const float* __restrict__ bihD, const float* __restrict__ bhhD,
    const float* __restrict__ Wlt,  const float* __restrict__ blt,
    const float* __restrict__ Wtl,  const float* __restrict__ btl,
    float* __restrict__ out)
{
    extern __shared__ float4 s_w[];  // 32KB Whh row cache (per-block rows)
    __shared__ float s_g[8];
    __shared__ float s_v[256];
    __shared__ int   s_i[256];
    __shared__ float s_sc[SLEN];
    __shared__ float s_a[SLEN];
    __shared__ float s_scalar[1];

    unsigned int gen = 0;
    float* out_logits = out + STEPS;
    const int b = blockIdx.x;
    const int w = threadIdx.x >> 5, lane = threadIdx.x & 31;
    int wid = 0, done = 0;

    // ---- P0: convert W_lt/W_li to fp16; precompute Wih_e @ x_t; stage WhhE ----
    convert_w16(Wlt, g_wlt16);
    convert_w16(Wli, g_wli16);
    stage_whh(WhhE, s_w);
    {
        const int r = b * NWARP + w;
        const float4* wr = (const float4*)(WihE + (size_t)r * H);
        float4 wreg[8];
#pragma unroll
        for (int q = 0; q < 8; q++) wreg[q] = wr[lane + 32 * q];
        for (int t = 0; t < SLEN; t += 2) {
            const float4* x0 = (const float4*)(embI + (size_t)src[t]     * H);
            const float4* x1 = (const float4*)(embI + (size_t)src[t + 1] * H);
            float a0 = 0.f, a1 = 0.f;
#pragma unroll
            for (int q = 0; q < 8; q++) {
                const int k = lane + 32 * q;
                a0 += dp4(wreg[q], x0[k]);
                a1 += dp4(wreg[q], x1[k]);
            }
            a0 = wred(a0);
            a1 = wred(a1);
            if (!lane) {
                g_gih[(size_t)t       * (4 * H) + r] = a0;
                g_gih[(size_t)(t + 1) * (4 * H) + r] = a1;
            }
        }
    }
    gbar(gen);

    // ---- encoder: 128 steps, Whh GEMV from SMEM + precomputed Wih term ----
    for (int t = 0; t < SLEN; t++) {
        lstm_whh_sm(s_w, g_hbuf[t & 1], s_g);
        lstm_pointwise_pre(t, bihE, bhhE, g_hbuf[(t + 1) & 1], g_hs + (size_t)t * H, s_g);
        gbar(gen);
    }
    // final encoder h in g_hbuf[0], c in g_c

    // ---- E1: first-word logits (fp16 Wli); re-stage cache with WhhD ----
    logits_piece_h(g_wli16, bli, g_hbuf[0], nullptr, s_v, s_i);
    __syncthreads();
    stage_whh(WhhD, s_w);
    gbar(gen);

    // ---- E2: replicated finalize -> wid0; initial decoder LSTM -> ht(0); U precompute ----
    finalize_repl(-1, wid, done, out, s_v, s_i);
    lstm_full_sm(WihD, s_w, bihD, bhhD, embT + (size_t)wid * H,
                 g_hbuf[0], g_hbuf[1], nullptr, s_g);
    u_precompute(Wtl);
    gbar(gen);

    // ---- E3: scores(0) ----
    scores_piece(g_hbuf[1]);
    gbar(gen);

    // ---- decode loop: 2 grid barriers per step ----
    int cur = 1;                                    // ht(t) = g_hbuf[cur]
    for (int t = 0; t < STEPS; t++) {
        const float* ht  = g_hbuf[cur];
        float*       htn = g_hbuf[1 - cur];

        // Phase A: finalize(t-1); full LSTM (Whh smem) -> ht(t+1); combine -> ht2(t)
        if (t > 0) finalize_repl(t - 1, wid, done, out, s_v, s_i);
        lstm_full_sm(WihD, s_w, bihD, bhhD, embT + (size_t)wid * H, ht, htn, nullptr, s_g);
        combine_piece(Wtl, btl, ht, s_sc, s_a, s_scalar);
        gbar(gen);

        // Phase B: logits(t) from ht2 over fp16 weights || scores(t+1) (blocks 496..511)
        scores_piece(htn);
        logits_piece_h(g_wlt16, blt, g_ht2, out_logits + (size_t)t * VOCAB, s_v, s_i);
        gbar(gen);

        cur ^= 1;
    }
    finalize_repl(STEPS - 1, wid, done, out, s_v, s_i);
}

// ---------------- host orchestration ----------------
extern "C" void kernel_launch(void* const* d_in, const int* in_sizes, int n_in,
                              void* d_out, int out_size)
{
    const int*   src  = (const int*)  d_in[0];
    const float* embI = (const float*)d_in[1];
    const float* WihE = (const float*)d_in[2];
    const float* WhhE = (const float*)d_in[3];
    const float* bihE = (const float*)d_in[4];
    const float* bhhE = (const float*)d_in[5];
    const float* Wli  = (const float*)d_in[6];
    const float* bli  = (const float*)d_in[7];
    const float* embT = (const float*)d_in[8];
    const float* WihD = (const float*)d_in[9];
    const float* WhhD = (const float*)d_in[10];
    const float* bihD = (const float*)d_in[11];
    const float* bhhD = (const float*)d_in[12];
    const float* Wlt  = (const float*)d_in[13];
    const float* blt  = (const float*)d_in[14];
    const float* Wtl  = (const float*)d_in[15];
    const float* btl  = (const float*)d_in[16];

    k_init<<<1, 1024>>>();
    k_main<<<GRID, TPB, WCACHE_BYTES>>>(src, embI, WihE, WhhE, bihE, bhhE, Wli, bli, embT,
                                        WihD, WhhD, bihD, bhhD, Wlt, blt, Wtl, btl,
                                        (float*)d_out);
}